// round 3
// baseline (speedup 1.0000x reference)
#include <cuda_runtime.h>
#include <cuda_bf16.h>

#define BMAX 32
#define NMAX 640
#define TB   16         // frames per block
#define NT   192        // threads per block (E = 384 = 2*NT)

// Scratch (allocation-free rule: __device__ globals)
__device__ float g_c[BMAX][NMAX];      // token centers
__device__ float g_rsig[BMAX][NMAX];   // 1/sigma
__device__ float g_coef[BMAX][NMAX];   // pad? 0 : 1/(sigma*sqrt(2pi))
__device__ int   g_tok[BMAX][NMAX];    // merged token ids
__device__ float g_cumtot[BMAX];       // total duration per batch

// ---------------------------------------------------------------------------
// Kernel 1: merge blank/token pairs + cumsum + per-token params. One block/batch.
// ---------------------------------------------------------------------------
__global__ void prep_kernel(const int* __restrict__ text,
                            const int* __restrict__ durs,
                            int L, int N) {
    const int b   = blockIdx.x;
    const int tid = threadIdx.x;   // blockDim.x == 1024

    float dm = 0.f;
    int   tk = 0;
    if (tid < N) {
        if (tid == 0) {
            dm = (float)durs[b * L];
            tk = text[b * L];
        } else {
            dm = (float)(durs[b * L + 2 * tid - 1] + durs[b * L + 2 * tid]);
            tk = text[b * L + 2 * tid - 1];
        }
    }

    __shared__ float s[1024];
    s[tid] = (tid < N) ? dm : 0.f;
    for (int off = 1; off < 1024; off <<= 1) {
        __syncthreads();
        float v = (tid >= off) ? s[tid - off] : 0.f;
        __syncthreads();
        s[tid] += v;
    }
    __syncthreads();

    if (tid < N) {
        float cum = s[tid];
        float sig = dm * 0.5f + 1e-6f;          // d / SIGMA_C + EPS, SIGMA_C = 2
        g_c[b][tid]    = cum - 0.5f * dm;
        g_rsig[b][tid] = 1.0f / sig;
        g_coef[b][tid] = (tk == 0) ? 0.f : (0.3989422804014327f / sig);
        g_tok[b][tid]  = tk;
        if (tid == N - 1) g_cumtot[b] = cum;
    }
}

// ---------------------------------------------------------------------------
// Kernel 2: one block per (b, 16 frames). 192 threads; thread owns output dims
// {tid, tid+192} for all 16 frames (32 accumulators). Single pass: accumulate
// with RAW Gaussian weights, normalize the accumulators at the end.
// ---------------------------------------------------------------------------
__global__ void __launch_bounds__(NT)
lenreg_kernel(const float* __restrict__ emb,
              float* __restrict__ out,
              int T, int N) {
    const int b   = blockIdx.y;
    const int t0  = blockIdx.x * TB;
    const int tid = threadIdx.x;

    float* obase = out + ((size_t)b * T + t0) * 384;
    const float cumtot = g_cumtot[b];

    // Entire block beyond sample duration -> zeros and exit (~25% of blocks)
    if ((float)t0 + 0.5f >= cumtot) {
        #pragma unroll
        for (int tt = 0; tt < TB; tt++) {
            float* orow = obase + tt * 384;
            orow[tid] = 0.f; orow[tid + NT] = 0.f;
        }
        return;
    }

    const float* __restrict__ cb    = g_c[b];
    const float* __restrict__ rsigb = g_rsig[b];
    const float* __restrict__ coefb = g_coef[b];
    const int*   __restrict__ tokb  = g_tok[b];

    // Window for the 16-frame group. Contributions beyond |t-c| > 28 are
    // < 1e-13 relative even against an eps-only denominator (sigma <= 3).
    const float t0f = (float)t0;
    const float tlo = t0f + 0.5f - 28.f;
    const float thi = t0f + ((float)TB - 0.5f) + 28.f;

    int lo = 0, hi = N;
    while (lo < hi) { int m = (lo + hi) >> 1; if (cb[m] < tlo) lo = m + 1; else hi = m; }
    const int nlo = lo;
    hi = N;
    while (lo < hi) { int m = (lo + hi) >> 1; if (cb[m] <= thi) lo = m + 1; else hi = m; }
    const int nhi = lo - 1;

    __shared__ float4 Wt4[NT * 4];     // [token][frame/4] raw weights
    __shared__ int    off_s[NT];       // byte offsets into emb table
    __shared__ float  ssum[TB];        // per-frame raw weight sums
    __shared__ float  sinv[TB];

    float a0[TB], a1[TB];
    #pragma unroll
    for (int tt = 0; tt < TB; tt++) { a0[tt] = 0.f; a1[tt] = 0.f; }

    if (tid < TB) ssum[tid] = 0.f;
    __syncthreads();

    for (int base = nlo; base <= nhi; base += NT) {
        const int n = base + tid;
        // ---- stage raw weights for own token ----
        if (n <= nhi) {
            const float c  = cb[n];
            const float rs = rsigb[n];
            const float cf = coefb[n];
            #pragma unroll
            for (int q = 0; q < 4; q++) {
                float4 wv;
                float z0 = (t0f + (float)(4 * q + 0) + 0.5f - c) * rs;
                float z1 = (t0f + (float)(4 * q + 1) + 0.5f - c) * rs;
                float z2 = (t0f + (float)(4 * q + 2) + 0.5f - c) * rs;
                float z3 = (t0f + (float)(4 * q + 3) + 0.5f - c) * rs;
                wv.x = cf * __expf(-0.5f * z0 * z0);
                wv.y = cf * __expf(-0.5f * z1 * z1);
                wv.z = cf * __expf(-0.5f * z2 * z2);
                wv.w = cf * __expf(-0.5f * z3 * z3);
                Wt4[tid * 4 + q] = wv;
            }
            off_s[tid] = tokb[n] * 1536;   // *384 floats *4 bytes
        }
        __syncthreads();

        const int cnt = min(NT, nhi - base + 1);

        // ---- per-frame raw-weight sums (6 warps cover 16 frames) ----
        {
            const int wrp  = tid >> 5;
            const int lane = tid & 31;
            const float* Wtf = (const float*)Wt4;
            for (int tt = wrp; tt < TB; tt += 6) {
                float s = 0.f;
                for (int j = lane; j < cnt; j += 32) s += Wtf[j * TB + tt];
                #pragma unroll
                for (int o = 16; o; o >>= 1) s += __shfl_down_sync(0xffffffffu, s, o);
                if (lane == 0) atomicAdd(&ssum[tt], s);
            }
        }

        // ---- accumulate: 32 FMAs per token against 2 embedding loads ----
        #pragma unroll 2
        for (int j = 0; j < cnt; j++) {
            const float* er = (const float*)((const char*)emb + off_s[j]);
            const float e0 = er[tid];
            const float e1 = er[tid + NT];
            const float4 w0 = Wt4[j * 4 + 0];
            const float4 w1 = Wt4[j * 4 + 1];
            const float4 w2 = Wt4[j * 4 + 2];
            const float4 w3 = Wt4[j * 4 + 3];
            a0[0]  += w0.x * e0;  a0[1]  += w0.y * e0;  a0[2]  += w0.z * e0;  a0[3]  += w0.w * e0;
            a0[4]  += w1.x * e0;  a0[5]  += w1.y * e0;  a0[6]  += w1.z * e0;  a0[7]  += w1.w * e0;
            a0[8]  += w2.x * e0;  a0[9]  += w2.y * e0;  a0[10] += w2.z * e0;  a0[11] += w2.w * e0;
            a0[12] += w3.x * e0;  a0[13] += w3.y * e0;  a0[14] += w3.z * e0;  a0[15] += w3.w * e0;
            a1[0]  += w0.x * e1;  a1[1]  += w0.y * e1;  a1[2]  += w0.z * e1;  a1[3]  += w0.w * e1;
            a1[4]  += w1.x * e1;  a1[5]  += w1.y * e1;  a1[6]  += w1.z * e1;  a1[7]  += w1.w * e1;
            a1[8]  += w2.x * e1;  a1[9]  += w2.y * e1;  a1[10] += w2.z * e1;  a1[11] += w2.w * e1;
            a1[12] += w3.x * e1;  a1[13] += w3.y * e1;  a1[14] += w3.z * e1;  a1[15] += w3.w * e1;
        }
        __syncthreads();   // protect Wt before next chunk overwrites
    }

    // ---- deferred normalization ----
    if (tid < TB) {
        float t = t0f + (float)tid + 0.5f;
        sinv[tid] = (t < cumtot) ? 1.0f / (ssum[tid] + 1e-6f) : 0.f;
    }
    __syncthreads();

    #pragma unroll
    for (int tt = 0; tt < TB; tt++) {
        const float inv = sinv[tt];
        float* orow = obase + tt * 384;
        orow[tid]      = a0[tt] * inv;
        orow[tid + NT] = a1[tt] * inv;
    }
}

// ---------------------------------------------------------------------------
extern "C" void kernel_launch(void* const* d_in, const int* in_sizes, int n_in,
                              void* d_out, int out_size) {
    const int*   text = (const int*)d_in[0];
    const int*   durs = (const int*)d_in[1];
    const float* emb  = (const float*)d_in[2];
    float* out = (float*)d_out;

    const int B = 32;
    const int L = in_sizes[0] / B;        // 1025
    const int N = (L + 1) / 2;            // 513
    const int T = out_size / (B * 384);   // 2048

    prep_kernel<<<B, 1024>>>(text, durs, L, N);

    dim3 grid(T / TB, B);
    lenreg_kernel<<<grid, NT>>>(emb, out, T, N);
}

// round 4
// speedup vs baseline: 1.3066x; 1.3066x over previous
#include <cuda_runtime.h>
#include <cuda_bf16.h>

#define BMAX 32
#define NMAX 640
#define TB   8          // frames per block
#define NT   128        // threads per block (E = 384 = 3*NT)

// Scratch (allocation-free rule: __device__ globals)
__device__ float g_c[BMAX][NMAX];      // token centers
__device__ float g_rsig[BMAX][NMAX];   // 1/sigma
__device__ float g_coef[BMAX][NMAX];   // pad? 0 : 1/(sigma*sqrt(2pi))
__device__ int   g_tok[BMAX][NMAX];    // merged token ids
__device__ float g_cumtot[BMAX];       // total duration per batch

// ---------------------------------------------------------------------------
// Kernel 1: merge blank/token pairs + cumsum + per-token params. One block/batch.
// ---------------------------------------------------------------------------
__global__ void prep_kernel(const int* __restrict__ text,
                            const int* __restrict__ durs,
                            int L, int N) {
    const int b   = blockIdx.x;
    const int tid = threadIdx.x;   // blockDim.x == 1024

    float dm = 0.f;
    int   tk = 0;
    if (tid < N) {
        if (tid == 0) {
            dm = (float)durs[b * L];
            tk = text[b * L];
        } else {
            dm = (float)(durs[b * L + 2 * tid - 1] + durs[b * L + 2 * tid]);
            tk = text[b * L + 2 * tid - 1];
        }
    }

    __shared__ float s[1024];
    s[tid] = (tid < N) ? dm : 0.f;
    for (int off = 1; off < 1024; off <<= 1) {
        __syncthreads();
        float v = (tid >= off) ? s[tid - off] : 0.f;
        __syncthreads();
        s[tid] += v;
    }
    __syncthreads();

    if (tid < N) {
        float cum = s[tid];
        float sig = dm * 0.5f + 1e-6f;          // d / SIGMA_C + EPS, SIGMA_C = 2
        g_c[b][tid]    = cum - 0.5f * dm;
        g_rsig[b][tid] = 1.0f / sig;
        g_coef[b][tid] = (tk == 0) ? 0.f : (0.3989422804014327f / sig);
        g_tok[b][tid]  = tk;
        if (tid == N - 1) g_cumtot[b] = cum;
    }
}

// ---------------------------------------------------------------------------
// Kernel 2: one block per (b, 8 frames). 128 threads; thread owns output dims
// {tid, tid+128, tid+256} for all 8 frames (24 accumulators). Single pass:
// accumulate with RAW Gaussian weights, normalize the accumulators at the end.
// ---------------------------------------------------------------------------
__global__ void __launch_bounds__(NT)
lenreg_kernel(const float* __restrict__ emb,
              float* __restrict__ out,
              int T, int N) {
    const int b   = blockIdx.y;
    const int t0  = blockIdx.x * TB;
    const int tid = threadIdx.x;

    float* obase = out + ((size_t)b * T + t0) * 384;
    const float cumtot = g_cumtot[b];

    // Entire block beyond sample duration -> zeros and exit (~25% of blocks)
    if ((float)t0 + 0.5f >= cumtot) {
        #pragma unroll
        for (int tt = 0; tt < TB; tt++) {
            float* orow = obase + tt * 384;
            orow[tid] = 0.f; orow[tid + 128] = 0.f; orow[tid + 256] = 0.f;
        }
        return;
    }

    const float* __restrict__ cb    = g_c[b];
    const float* __restrict__ rsigb = g_rsig[b];
    const float* __restrict__ coefb = g_coef[b];
    const int*   __restrict__ tokb  = g_tok[b];

    // Window: every valid frame has a non-pad contributor within ~6 frames
    // (w >= 0.018); a token truncated at |t-c| = 18 has w <= 0.133*e^-18
    // => relative contribution <= ~1e-7, far below the 1e-3 gate.
    const float t0f = (float)t0;
    const float W   = 18.f;
    const float tlo = t0f + 0.5f - W;
    const float thi = t0f + ((float)TB - 0.5f) + W;

    int lo = 0, hi = N;
    while (lo < hi) { int m = (lo + hi) >> 1; if (cb[m] < tlo) lo = m + 1; else hi = m; }
    const int nlo = lo;
    hi = N;
    while (lo < hi) { int m = (lo + hi) >> 1; if (cb[m] <= thi) lo = m + 1; else hi = m; }
    const int nhi = lo - 1;

    __shared__ float4 Wt4[NT * 2];     // [token][frame/4] raw weights (8 frames)
    __shared__ int    off_s[NT];       // byte offsets into emb table
    __shared__ float  ssum[TB];        // per-frame raw weight sums
    __shared__ float  sinv[TB];

    float a0[TB], a1[TB], a2[TB];
    #pragma unroll
    for (int tt = 0; tt < TB; tt++) { a0[tt] = 0.f; a1[tt] = 0.f; a2[tt] = 0.f; }

    if (tid < TB) ssum[tid] = 0.f;
    __syncthreads();

    for (int base = nlo; base <= nhi; base += NT) {
        const int n = base + tid;
        // ---- stage raw weights for own token ----
        if (n <= nhi) {
            const float c  = cb[n];
            const float rs = rsigb[n];
            const float cf = coefb[n];
            #pragma unroll
            for (int q = 0; q < 2; q++) {
                float4 wv;
                float z0 = (t0f + (float)(4 * q + 0) + 0.5f - c) * rs;
                float z1 = (t0f + (float)(4 * q + 1) + 0.5f - c) * rs;
                float z2 = (t0f + (float)(4 * q + 2) + 0.5f - c) * rs;
                float z3 = (t0f + (float)(4 * q + 3) + 0.5f - c) * rs;
                wv.x = cf * __expf(-0.5f * z0 * z0);
                wv.y = cf * __expf(-0.5f * z1 * z1);
                wv.z = cf * __expf(-0.5f * z2 * z2);
                wv.w = cf * __expf(-0.5f * z3 * z3);
                Wt4[tid * 2 + q] = wv;
            }
            off_s[tid] = tokb[n] * 1536;   // *384 floats *4 bytes
        }
        __syncthreads();

        const int cnt = min(NT, nhi - base + 1);

        // ---- per-frame raw-weight sums (4 warps cover 8 frames) ----
        {
            const int wrp  = tid >> 5;
            const int lane = tid & 31;
            const float* Wtf = (const float*)Wt4;
            #pragma unroll
            for (int k = 0; k < 2; k++) {
                const int tt = wrp + 4 * k;
                float s = 0.f;
                for (int j = lane; j < cnt; j += 32) s += Wtf[j * TB + tt];
                #pragma unroll
                for (int o = 16; o; o >>= 1) s += __shfl_down_sync(0xffffffffu, s, o);
                if (lane == 0) atomicAdd(&ssum[tt], s);
            }
        }

        // ---- accumulate: 24 FMAs per token against 3 embedding loads ----
        #pragma unroll 2
        for (int j = 0; j < cnt; j++) {
            const float* er = (const float*)((const char*)emb + off_s[j]);
            const float e0 = er[tid];
            const float e1 = er[tid + 128];
            const float e2 = er[tid + 256];
            const float4 w0 = Wt4[j * 2 + 0];
            const float4 w1 = Wt4[j * 2 + 1];
            a0[0] += w0.x * e0; a0[1] += w0.y * e0; a0[2] += w0.z * e0; a0[3] += w0.w * e0;
            a0[4] += w1.x * e0; a0[5] += w1.y * e0; a0[6] += w1.z * e0; a0[7] += w1.w * e0;
            a1[0] += w0.x * e1; a1[1] += w0.y * e1; a1[2] += w0.z * e1; a1[3] += w0.w * e1;
            a1[4] += w1.x * e1; a1[5] += w1.y * e1; a1[6] += w1.z * e1; a1[7] += w1.w * e1;
            a2[0] += w0.x * e2; a2[1] += w0.y * e2; a2[2] += w0.z * e2; a2[3] += w0.w * e2;
            a2[4] += w1.x * e2; a2[5] += w1.y * e2; a2[6] += w1.z * e2; a2[7] += w1.w * e2;
        }
        __syncthreads();   // protect Wt before next chunk overwrites
    }

    // ---- deferred normalization ----
    if (tid < TB) {
        float t = t0f + (float)tid + 0.5f;
        sinv[tid] = (t < cumtot) ? 1.0f / (ssum[tid] + 1e-6f) : 0.f;
    }
    __syncthreads();

    #pragma unroll
    for (int tt = 0; tt < TB; tt++) {
        const float inv = sinv[tt];
        float* orow = obase + tt * 384;
        orow[tid]       = a0[tt] * inv;
        orow[tid + 128] = a1[tt] * inv;
        orow[tid + 256] = a2[tt] * inv;
    }
}

// ---------------------------------------------------------------------------
extern "C" void kernel_launch(void* const* d_in, const int* in_sizes, int n_in,
                              void* d_out, int out_size) {
    const int*   text = (const int*)d_in[0];
    const int*   durs = (const int*)d_in[1];
    const float* emb  = (const float*)d_in[2];
    float* out = (float*)d_out;

    const int B = 32;
    const int L = in_sizes[0] / B;        // 1025
    const int N = (L + 1) / 2;            // 513
    const int T = out_size / (B * 384);   // 2048

    prep_kernel<<<B, 1024>>>(text, durs, L, N);

    dim3 grid(T / TB, B);
    lenreg_kernel<<<grid, NT>>>(emb, out, T, N);
}

// round 5
// speedup vs baseline: 1.4971x; 1.1457x over previous
#include <cuda_runtime.h>
#include <cuda_bf16.h>

#define BMAX 32
#define NMAX 640
#define GMAX 512        // max frame-groups per batch
#define TB   8          // frames per block
#define NT   128        // threads per block (E = 384 = 3*NT)

// Scratch (allocation-free rule: __device__ globals)
__device__ float g_c[BMAX][NMAX];      // token centers
__device__ float g_rsig[BMAX][NMAX];   // 1/sigma
__device__ float g_coef[BMAX][NMAX];   // pad? 0 : 1/(sigma*sqrt(2pi))
__device__ int   g_tok[BMAX][NMAX];    // merged token ids
__device__ float g_cumtot[BMAX];       // total duration per batch
__device__ int2  g_win[BMAX][GMAX];    // per frame-group token window [nlo, nhi]

// ---------------------------------------------------------------------------
// Kernel 1: merge blank/token pairs + cumsum + per-token params. One block/batch.
// ---------------------------------------------------------------------------
__global__ void prep_kernel(const int* __restrict__ text,
                            const int* __restrict__ durs,
                            int L, int N) {
    const int b   = blockIdx.x;
    const int tid = threadIdx.x;   // blockDim.x == 1024

    float dm = 0.f;
    int   tk = 0;
    if (tid < N) {
        if (tid == 0) {
            dm = (float)durs[b * L];
            tk = text[b * L];
        } else {
            dm = (float)(durs[b * L + 2 * tid - 1] + durs[b * L + 2 * tid]);
            tk = text[b * L + 2 * tid - 1];
        }
    }

    __shared__ float s[1024];
    s[tid] = (tid < N) ? dm : 0.f;
    for (int off = 1; off < 1024; off <<= 1) {
        __syncthreads();
        float v = (tid >= off) ? s[tid - off] : 0.f;
        __syncthreads();
        s[tid] += v;
    }
    __syncthreads();

    if (tid < N) {
        float cum = s[tid];
        float sig = dm * 0.5f + 1e-6f;          // d / SIGMA_C + EPS, SIGMA_C = 2
        g_c[b][tid]    = cum - 0.5f * dm;
        g_rsig[b][tid] = 1.0f / sig;
        g_coef[b][tid] = (tk == 0) ? 0.f : (0.3989422804014327f / sig);
        g_tok[b][tid]  = tk;
        if (tid == N - 1) g_cumtot[b] = cum;
    }
}

// ---------------------------------------------------------------------------
// Kernel 1b: per (b, frame-group) token window via binary search. Fully
// parallel -> memory latency overlapped across 8192 independent threads.
// Window: every valid frame has a non-pad contributor within ~6 frames
// (w >= 0.018); a token truncated at |t-c| = 18 has w <= 0.133*e^-18
// => relative contribution <= ~1e-7, far below the 1e-3 gate.
// ---------------------------------------------------------------------------
__global__ void win_kernel(int B, int G, int N) {
    const int idx = blockIdx.x * blockDim.x + threadIdx.x;
    if (idx >= B * G) return;
    const int b = idx / G;
    const int g = idx % G;

    const float* __restrict__ cb = g_c[b];
    const float t0f = (float)(g * TB);
    const float tlo = t0f + 0.5f - 18.f;
    const float thi = t0f + ((float)TB - 0.5f) + 18.f;

    int lo = 0, hi = N;
    while (lo < hi) { int m = (lo + hi) >> 1; if (cb[m] < tlo) lo = m + 1; else hi = m; }
    const int nlo = lo;
    hi = N;
    while (lo < hi) { int m = (lo + hi) >> 1; if (cb[m] <= thi) lo = m + 1; else hi = m; }
    g_win[b][g] = make_int2(nlo, lo - 1);
}

// ---------------------------------------------------------------------------
// Kernel 2: one block per (b, 8 frames). 128 threads; thread owns output dims
// {tid, tid+128, tid+256} for all 8 frames (24 accumulators). Single pass:
// accumulate with RAW weights; every thread also accumulates the per-frame
// weight sums redundantly (kills the shuffle/atomic reduction); normalize at
// the end.
// ---------------------------------------------------------------------------
__global__ void __launch_bounds__(NT)
lenreg_kernel(const float* __restrict__ emb,
              float* __restrict__ out,
              int T, int N) {
    const int b   = blockIdx.y;
    const int t0  = blockIdx.x * TB;
    const int tid = threadIdx.x;

    float* obase = out + ((size_t)b * T + t0) * 384;
    const float cumtot = g_cumtot[b];

    // Entire block beyond sample duration -> zeros and exit (~25% of blocks)
    if ((float)t0 + 0.5f >= cumtot) {
        #pragma unroll
        for (int tt = 0; tt < TB; tt++) {
            float* orow = obase + tt * 384;
            orow[tid] = 0.f; orow[tid + 128] = 0.f; orow[tid + 256] = 0.f;
        }
        return;
    }

    const float* __restrict__ cb    = g_c[b];
    const float* __restrict__ rsigb = g_rsig[b];
    const float* __restrict__ coefb = g_coef[b];
    const int*   __restrict__ tokb  = g_tok[b];

    const int2  win = g_win[b][blockIdx.x];
    const int   nlo = win.x;
    const int   nhi = win.y;
    const float t0f = (float)t0;

    __shared__ float4 Wt4[NT * 2];     // [token][frame/4] raw weights (8 frames)
    __shared__ int    off_s[NT];       // byte offsets into emb table

    float a0[TB], a1[TB], a2[TB], ws[TB];
    #pragma unroll
    for (int tt = 0; tt < TB; tt++) { a0[tt] = 0.f; a1[tt] = 0.f; a2[tt] = 0.f; ws[tt] = 0.f; }

    for (int base = nlo; base <= nhi; base += NT) {
        const int n = base + tid;
        // ---- stage raw weights for own token ----
        if (n <= nhi) {
            const float c  = cb[n];
            const float rs = rsigb[n];
            const float cf = coefb[n];
            #pragma unroll
            for (int q = 0; q < 2; q++) {
                float4 wv;
                float z0 = (t0f + (float)(4 * q + 0) + 0.5f - c) * rs;
                float z1 = (t0f + (float)(4 * q + 1) + 0.5f - c) * rs;
                float z2 = (t0f + (float)(4 * q + 2) + 0.5f - c) * rs;
                float z3 = (t0f + (float)(4 * q + 3) + 0.5f - c) * rs;
                wv.x = cf * __expf(-0.5f * z0 * z0);
                wv.y = cf * __expf(-0.5f * z1 * z1);
                wv.z = cf * __expf(-0.5f * z2 * z2);
                wv.w = cf * __expf(-0.5f * z3 * z3);
                Wt4[tid * 2 + q] = wv;
            }
            off_s[tid] = tokb[n] * 1536;   // *384 floats *4 bytes
        }
        __syncthreads();

        const int cnt = min(NT, nhi - base + 1);

        // ---- accumulate: 24 FMA + 8 FADD per token against 3 embedding loads
        #pragma unroll 2
        for (int j = 0; j < cnt; j++) {
            const float* er = (const float*)((const char*)emb + off_s[j]);
            const float e0 = er[tid];
            const float e1 = er[tid + 128];
            const float e2 = er[tid + 256];
            const float4 w0 = Wt4[j * 2 + 0];
            const float4 w1 = Wt4[j * 2 + 1];
            ws[0] += w0.x; ws[1] += w0.y; ws[2] += w0.z; ws[3] += w0.w;
            ws[4] += w1.x; ws[5] += w1.y; ws[6] += w1.z; ws[7] += w1.w;
            a0[0] += w0.x * e0; a0[1] += w0.y * e0; a0[2] += w0.z * e0; a0[3] += w0.w * e0;
            a0[4] += w1.x * e0; a0[5] += w1.y * e0; a0[6] += w1.z * e0; a0[7] += w1.w * e0;
            a1[0] += w0.x * e1; a1[1] += w0.y * e1; a1[2] += w0.z * e1; a1[3] += w0.w * e1;
            a1[4] += w1.x * e1; a1[5] += w1.y * e1; a1[6] += w1.z * e1; a1[7] += w1.w * e1;
            a2[0] += w0.x * e2; a2[1] += w0.y * e2; a2[2] += w0.z * e2; a2[3] += w0.w * e2;
            a2[4] += w1.x * e2; a2[5] += w1.y * e2; a2[6] += w1.z * e2; a2[7] += w1.w * e2;
        }
        if (base + NT <= nhi) __syncthreads();   // only if another chunk follows
    }

    // ---- deferred normalization (per-thread, no shared) ----
    #pragma unroll
    for (int tt = 0; tt < TB; tt++) {
        const bool  valid = (t0f + (float)tt + 0.5f) < cumtot;
        const float inv   = valid ? 1.0f / (ws[tt] + 1e-6f) : 0.f;
        float* orow = obase + tt * 384;
        orow[tid]       = a0[tt] * inv;
        orow[tid + 128] = a1[tt] * inv;
        orow[tid + 256] = a2[tt] * inv;
    }
}

// ---------------------------------------------------------------------------
extern "C" void kernel_launch(void* const* d_in, const int* in_sizes, int n_in,
                              void* d_out, int out_size) {
    const int*   text = (const int*)d_in[0];
    const int*   durs = (const int*)d_in[1];
    const float* emb  = (const float*)d_in[2];
    float* out = (float*)d_out;

    const int B = 32;
    const int L = in_sizes[0] / B;        // 1025
    const int N = (L + 1) / 2;            // 513
    const int T = out_size / (B * 384);   // 2048
    const int G = T / TB;                 // 256 frame-groups per batch

    prep_kernel<<<B, 1024>>>(text, durs, L, N);
    win_kernel<<<(B * G + 255) / 256, 256>>>(B, G, N);

    dim3 grid(G, B);
    lenreg_kernel<<<grid, NT>>>(emb, out, T, N);
}

// round 6
// speedup vs baseline: 1.7103x; 1.1424x over previous
#include <cuda_runtime.h>
#include <cuda_bf16.h>

#define BMAX 32
#define NMAX 640
#define GMAX 512        // max frame-groups per batch
#define TB   8          // frames per block
#define NT   128        // threads per block (E = 384 = 3*NT)

// Scratch (allocation-free rule: __device__ globals)
__device__ float g_c[BMAX][NMAX];      // compacted token centers
__device__ float g_rsig[BMAX][NMAX];   // 1/sigma
__device__ float g_coef[BMAX][NMAX];   // 1/(sigma*sqrt(2pi))
__device__ int   g_tok[BMAX][NMAX];    // merged token ids (compacted)
__device__ float g_cumtot[BMAX];       // total duration per batch
__device__ int2  g_win[BMAX][GMAX];    // per frame-group token window [nlo, nhi]

// ---------------------------------------------------------------------------
// Kernel 1 (fused): merge pairs + shuffle-scan cumsum + compaction of
// zero-weight tokens (pad or zero-duration: both contribute EXACTLY 0 weight;
// sigma=1e-6 gives |z|>=5e5 so expf underflows to 0 in fp32, matching the
// reference's own underflow) + per-group window binary search in shared mem.
// One block per batch, 1024 threads.
// ---------------------------------------------------------------------------
__global__ void __launch_bounds__(1024)
prep_kernel(const int* __restrict__ text,
            const int* __restrict__ durs,
            int L, int N, int G) {
    const int b    = blockIdx.x;
    const int tid  = threadIdx.x;
    const int wrp  = tid >> 5;
    const int lane = tid & 31;

    float dm = 0.f;
    int   tk = 0;
    if (tid < N) {
        if (tid == 0) {
            dm = (float)durs[b * L];
            tk = text[b * L];
        } else {
            dm = (float)(durs[b * L + 2 * tid - 1] + durs[b * L + 2 * tid]);
            tk = text[b * L + 2 * tid - 1];
        }
    }
    const int keep = (tid < N && tk != 0 && dm > 0.f) ? 1 : 0;

    // ---- two-level inclusive scan over (dm, keep) via shuffles ----
    __shared__ float s_wd[32];
    __shared__ int   s_wk[32];
    float cum = dm;
    int   pos = keep;
    #pragma unroll
    for (int off = 1; off < 32; off <<= 1) {
        float fv = __shfl_up_sync(0xffffffffu, cum, off);
        int   iv = __shfl_up_sync(0xffffffffu, pos, off);
        if (lane >= off) { cum += fv; pos += iv; }
    }
    if (lane == 31) { s_wd[wrp] = cum; s_wk[wrp] = pos; }
    __syncthreads();
    if (wrp == 0) {
        float fv = s_wd[lane];
        int   iv = s_wk[lane];
        #pragma unroll
        for (int off = 1; off < 32; off <<= 1) {
            float f2 = __shfl_up_sync(0xffffffffu, fv, off);
            int   i2 = __shfl_up_sync(0xffffffffu, iv, off);
            if (lane >= off) { fv += f2; iv += i2; }
        }
        s_wd[lane] = fv; s_wk[lane] = iv;
    }
    __syncthreads();
    if (wrp > 0) { cum += s_wd[wrp - 1]; pos += s_wk[wrp - 1]; }

    // ---- emit compacted token params ----
    __shared__ float s_c[NMAX];
    __shared__ int   s_n2;
    if (keep) {
        const int   o   = pos - 1;
        const float sig = dm * 0.5f + 1e-6f;     // d / SIGMA_C + EPS, SIGMA_C = 2
        const float c   = cum - 0.5f * dm;
        g_c[b][o]    = c;
        g_rsig[b][o] = 1.0f / sig;
        g_coef[b][o] = 0.3989422804014327f / sig;
        g_tok[b][o]  = tk;
        s_c[o]       = c;
    }
    if (tid == N - 1) { g_cumtot[b] = cum; s_n2 = pos; }
    __syncthreads();

    // ---- per frame-group windows via binary search in shared centers ----
    // Window |t-c| <= 18: truncated tokens contribute <= ~1e-7 relative
    // (every valid frame has a contributor within ~6 frames, w >= 0.018).
    if (tid < G) {
        const int   N2  = s_n2;
        const float t0f = (float)(tid * TB);
        const float tlo = t0f + 0.5f - 18.f;
        const float thi = t0f + ((float)TB - 0.5f) + 18.f;
        int lo = 0, hi = N2;
        while (lo < hi) { int m = (lo + hi) >> 1; if (s_c[m] < tlo) lo = m + 1; else hi = m; }
        const int nlo = lo;
        hi = N2;
        while (lo < hi) { int m = (lo + hi) >> 1; if (s_c[m] <= thi) lo = m + 1; else hi = m; }
        g_win[b][tid] = make_int2(nlo, lo - 1);
    }
}

// ---------------------------------------------------------------------------
// Kernel 2: one block per (b, 8 frames). 128 threads; thread owns output dims
// {tid, tid+128, tid+256} for all 8 frames (24 accumulators). Single pass:
// accumulate with RAW weights; per-frame weight sums accumulated redundantly
// per thread; normalize at the end.
// ---------------------------------------------------------------------------
__global__ void __launch_bounds__(NT)
lenreg_kernel(const float* __restrict__ emb,
              float* __restrict__ out,
              int T) {
    const int b   = blockIdx.y;
    const int t0  = blockIdx.x * TB;
    const int tid = threadIdx.x;

    float* obase = out + ((size_t)b * T + t0) * 384;
    const float cumtot = g_cumtot[b];

    // Entire block beyond sample duration -> zeros and exit (~25% of blocks)
    if ((float)t0 + 0.5f >= cumtot) {
        #pragma unroll
        for (int tt = 0; tt < TB; tt++) {
            float* orow = obase + tt * 384;
            orow[tid] = 0.f; orow[tid + 128] = 0.f; orow[tid + 256] = 0.f;
        }
        return;
    }

    const float* __restrict__ cb    = g_c[b];
    const float* __restrict__ rsigb = g_rsig[b];
    const float* __restrict__ coefb = g_coef[b];
    const int*   __restrict__ tokb  = g_tok[b];

    const int2  win = g_win[b][blockIdx.x];
    const int   nlo = win.x;
    const int   nhi = win.y;
    const float t0f = (float)t0;

    __shared__ float4 Wt4[NT * 2];     // [token][frame/4] raw weights (8 frames)
    __shared__ int    off_s[NT];       // byte offsets into emb table

    float a0[TB], a1[TB], a2[TB], ws[TB];
    #pragma unroll
    for (int tt = 0; tt < TB; tt++) { a0[tt] = 0.f; a1[tt] = 0.f; a2[tt] = 0.f; ws[tt] = 0.f; }

    for (int base = nlo; base <= nhi; base += NT) {
        const int n = base + tid;
        // ---- stage raw weights for own token ----
        if (n <= nhi) {
            const float c  = cb[n];
            const float rs = rsigb[n];
            const float cf = coefb[n];
            #pragma unroll
            for (int q = 0; q < 2; q++) {
                float4 wv;
                float z0 = (t0f + (float)(4 * q + 0) + 0.5f - c) * rs;
                float z1 = (t0f + (float)(4 * q + 1) + 0.5f - c) * rs;
                float z2 = (t0f + (float)(4 * q + 2) + 0.5f - c) * rs;
                float z3 = (t0f + (float)(4 * q + 3) + 0.5f - c) * rs;
                wv.x = cf * __expf(-0.5f * z0 * z0);
                wv.y = cf * __expf(-0.5f * z1 * z1);
                wv.z = cf * __expf(-0.5f * z2 * z2);
                wv.w = cf * __expf(-0.5f * z3 * z3);
                Wt4[tid * 2 + q] = wv;
            }
            off_s[tid] = tokb[n] * 1536;   // *384 floats *4 bytes
        }
        __syncthreads();

        const int cnt = min(NT, nhi - base + 1);

        // ---- accumulate: 24 FMA + 8 FADD per token against 3 embedding loads
        #pragma unroll 2
        for (int j = 0; j < cnt; j++) {
            const float* er = (const float*)((const char*)emb + off_s[j]);
            const float e0 = er[tid];
            const float e1 = er[tid + 128];
            const float e2 = er[tid + 256];
            const float4 w0 = Wt4[j * 2 + 0];
            const float4 w1 = Wt4[j * 2 + 1];
            ws[0] += w0.x; ws[1] += w0.y; ws[2] += w0.z; ws[3] += w0.w;
            ws[4] += w1.x; ws[5] += w1.y; ws[6] += w1.z; ws[7] += w1.w;
            a0[0] += w0.x * e0; a0[1] += w0.y * e0; a0[2] += w0.z * e0; a0[3] += w0.w * e0;
            a0[4] += w1.x * e0; a0[5] += w1.y * e0; a0[6] += w1.z * e0; a0[7] += w1.w * e0;
            a1[0] += w0.x * e1; a1[1] += w0.y * e1; a1[2] += w0.z * e1; a1[3] += w0.w * e1;
            a1[4] += w1.x * e1; a1[5] += w1.y * e1; a1[6] += w1.z * e1; a1[7] += w1.w * e1;
            a2[0] += w0.x * e2; a2[1] += w0.y * e2; a2[2] += w0.z * e2; a2[3] += w0.w * e2;
            a2[4] += w1.x * e2; a2[5] += w1.y * e2; a2[6] += w1.z * e2; a2[7] += w1.w * e2;
        }
        if (base + NT <= nhi) __syncthreads();   // only if another chunk follows
    }

    // ---- deferred normalization (per-thread, no shared) ----
    #pragma unroll
    for (int tt = 0; tt < TB; tt++) {
        const bool  valid = (t0f + (float)tt + 0.5f) < cumtot;
        const float inv   = valid ? 1.0f / (ws[tt] + 1e-6f) : 0.f;
        float* orow = obase + tt * 384;
        orow[tid]       = a0[tt] * inv;
        orow[tid + 128] = a1[tt] * inv;
        orow[tid + 256] = a2[tt] * inv;
    }
}

// ---------------------------------------------------------------------------
extern "C" void kernel_launch(void* const* d_in, const int* in_sizes, int n_in,
                              void* d_out, int out_size) {
    const int*   text = (const int*)d_in[0];
    const int*   durs = (const int*)d_in[1];
    const float* emb  = (const float*)d_in[2];
    float* out = (float*)d_out;

    const int B = 32;
    const int L = in_sizes[0] / B;        // 1025
    const int N = (L + 1) / 2;            // 513
    const int T = out_size / (B * 384);   // 2048
    const int G = T / TB;                 // 256 frame-groups per batch

    prep_kernel<<<B, 1024>>>(text, durs, L, N, G);

    dim3 grid(G, B);
    lenreg_kernel<<<grid, NT>>>(emb, out, T);
}